// round 10
// baseline (speedup 1.0000x reference)
#include <cuda_runtime.h>
#include <cuda_bf16.h>

// Problem dims
#define B_    512
#define T_    1024
#define DIN_  64
#define H_    256
#define MLPH_ 256
#define DOUT_ 64

// LSTM tiling: 16 groups x 8 CTAs; group = 32 batch rows; CTA = 32 units (128 gate cols)
// K = 320 = H + DIN (fused input projection)
#define LSTM_SMEM_FLOATS (320*128 + 320*32)           // Wsm + hxT
#define LSTM_SMEM_BYTES  (LSTM_SMEM_FLOATS * 4)       // 204800

// MLP smem: AT region 256*65 floats (max of GEMM1 stride-64 and y1T stride-65), BT 64*256
#define MLP_AT_FLOATS (256*65)                         // 16640
#define MLP_BT_FLOATS (64*256)                         // 16384
#define MLP_SMEM_BYTES ((MLP_AT_FLOATS + MLP_BT_FLOATS) * 4)  // 132096

// Device scratch (static; cudaMalloc is forbidden)
__device__ float    g_hbuf[2][B_][H_];                                  // double-buffered h
__device__ float    g_hs[(size_t)B_ * T_ * H_];                         // all hidden states
__device__ unsigned g_bar[16];                                          // per-group barrier

__device__ __forceinline__ float sigf(float v) {
    return __fdividef(1.0f, 1.0f + __expf(-v));
}

// ---------------------------------------------------------------------------
// init: h buffer <- h0, reset barriers (runs every launch -> replay-safe)
// ---------------------------------------------------------------------------
__global__ void init_kernel(const float* __restrict__ h0) {
    int i = blockIdx.x * 256 + threadIdx.x;
    if (i < B_ * H_) (&g_hbuf[0][0][0])[i] = h0[i];
    if (blockIdx.x == 0 && threadIdx.x < 16) g_bar[threadIdx.x] = 0u;
}

// ---------------------------------------------------------------------------
// Persistent LSTM: grid 128 (16 groups x 8), 256 threads, weights in SMEM
// ---------------------------------------------------------------------------
__global__ void __launch_bounds__(256, 1) lstm_kernel(
    const float* __restrict__ x,    const float* __restrict__ h0,
    const float* __restrict__ c0,   const float* __restrict__ W_ih,
    const float* __restrict__ W_hh, const float* __restrict__ b_ih,
    const float* __restrict__ b_hh)
{
    extern __shared__ float sm[];
    float* Wsm = sm;                 // [k=320][n=128], n = 4*local_unit + gate
    float* hxT = sm + 320 * 128;     // [k=320][m=32]

    const int tid = threadIdx.x;
    const int p   = blockIdx.x >> 3;   // batch group 0..15
    const int q   = blockIdx.x & 7;    // unit CTA   0..7
    const int b0  = p * 32;
    const int u0  = q * 32;
    const int tm  = tid >> 5;          // 0..7  (4 batch rows each)
    const int tn  = tid & 31;          // 0..31 (one hidden unit each)

    // One-time: weight slice into SMEM. n -> (unit = u0 + (n>>2), gate = n&3)
    for (int i = tid; i < 320 * 128; i += 256) {
        int k = i >> 7, n = i & 127;
        int grow = (n & 3) * H_ + u0 + (n >> 2);
        Wsm[i] = (k < H_) ? W_hh[grow * H_ + k]
                          : W_ih[grow * DIN_ + (k - H_)];
    }

    // Per-thread bias (i,f,g,o for unit u0+tn) and cell state (4 batch rows)
    float bs[4], c[4];
#pragma unroll
    for (int j = 0; j < 4; j++)
        bs[j] = b_ih[j * H_ + u0 + tn] + b_hh[j * H_ + u0 + tn];
#pragma unroll
    for (int i = 0; i < 4; i++)
        c[i] = c0[(size_t)(b0 + tm * 4 + i) * H_ + u0 + tn];

    __syncthreads();

    const float* ap = &hxT[tm * 4];
    const float* bp = &Wsm[tn * 4];
    unsigned cur = 0;

    for (int t = 0; t < T_; t++) {
        // Stage [h | x_t] transposed: hxT[k][m]. 2560 float4 tasks.
        for (int e = tid; e < 2560; e += 256) {
            int m = e & 31, kg = e >> 5;        // kg: 0..79 (k-quad)
            float4 v;
            if (kg < 64) {
                v = __ldcg((const float4*)&g_hbuf[cur][b0 + m][kg * 4]);
            } else {
                v = *(const float4*)&x[((size_t)(b0 + m) * T_ + t) * DIN_ + (kg - 64) * 4];
            }
            int k = kg * 4;
            hxT[(k + 0) * 32 + m] = v.x;
            hxT[(k + 1) * 32 + m] = v.y;
            hxT[(k + 2) * 32 + m] = v.z;
            hxT[(k + 3) * 32 + m] = v.w;
        }
        __syncthreads();

        // GEMM: [32 x 320] @ [320 x 128] -> thread tile 4m x (unit: 4 gates)
        float acc[4][4];
#pragma unroll
        for (int i = 0; i < 4; i++)
#pragma unroll
            for (int j = 0; j < 4; j++) acc[i][j] = bs[j];

#pragma unroll 4
        for (int k = 0; k < 320; k++) {
            float4 av = *(const float4*)(ap + k * 32);    // broadcast within warp
            float4 bv = *(const float4*)(bp + k * 128);   // conflict-free
            float aa[4] = {av.x, av.y, av.z, av.w};
            float bb[4] = {bv.x, bv.y, bv.z, bv.w};
#pragma unroll
            for (int i = 0; i < 4; i++)
#pragma unroll
                for (int j = 0; j < 4; j++)
                    acc[i][j] = fmaf(aa[i], bb[j], acc[i][j]);
        }
        __syncthreads();   // all reads of hxT done before next staging

        // Pointwise LSTM cell + h writes
        unsigned nxt = cur ^ 1u;
#pragma unroll
        for (int i = 0; i < 4; i++) {
            float ig = sigf(acc[i][0]);
            float fg = sigf(acc[i][1]);
            float gg = tanhf(acc[i][2]);
            float og = sigf(acc[i][3]);
            float cn = fmaf(fg, c[i], ig * gg);
            c[i] = cn;
            float h = og * tanhf(cn);
            int m = b0 + tm * 4 + i;
            g_hbuf[nxt][m][u0 + tn] = h;
            g_hs[((size_t)m * T_ + t) * H_ + u0 + tn] = h;
        }

        // Per-group barrier (monotonic counter; 8 arrivals per step)
        __threadfence();
        __syncthreads();
        if (tid == 0) {
            atomicAdd(&g_bar[p], 1u);
            unsigned target = 8u * (unsigned)(t + 1);
            unsigned v;
            do {
                asm volatile("ld.global.acquire.gpu.u32 %0, [%1];"
                             : "=r"(v) : "l"(g_bar + p));
            } while (v < target);
        }
        __syncthreads();
        cur = nxt;
    }
}

// ---------------------------------------------------------------------------
// Fused MLP: y = relu(hs @ W1^T + b1) @ W2^T + b2, * mask
// grid 8192 (64-row tiles), 256 threads
// ---------------------------------------------------------------------------
__global__ void __launch_bounds__(256, 1) mlp_kernel(
    const float* __restrict__ W1, const float* __restrict__ b1,
    const float* __restrict__ W2, const float* __restrict__ b2,
    const float* __restrict__ mask, float* __restrict__ out)
{
    extern __shared__ float sm[];
    float* AT = sm;                   // GEMM1: [k=256][m=64] stride 64; y1T: stride 65
    float* BT = sm + MLP_AT_FLOATS;   // [kk=64][n<=256]

    const int tid = threadIdx.x;
    const size_t row0 = (size_t)blockIdx.x * 64;
    const int tm = tid >> 5;          // 0..7  -> 8 m rows each
    const int tn = tid & 31;          // 0..31

    // Stage A tile transposed (lanes vary m -> conflict-free stores)
    for (int e = tid; e < 4096; e += 256) {
        int m = e & 63, kq = e >> 6;
        float4 v = *(const float4*)&g_hs[(row0 + m) * H_ + kq * 4];
        int k = kq * 4;
        AT[(k + 0) * 64 + m] = v.x;
        AT[(k + 1) * 64 + m] = v.y;
        AT[(k + 2) * 64 + m] = v.z;
        AT[(k + 3) * 64 + m] = v.w;
    }

    // ---- GEMM1: [64 x 256] @ [256 x 256], thread tile 8m x 8n ----
    float acc[8][8];
#pragma unroll
    for (int i = 0; i < 8; i++)
#pragma unroll
        for (int j = 0; j < 8; j++) acc[i][j] = 0.0f;

    for (int kb = 0; kb < H_; kb += 64) {
        __syncthreads();
        // Stage W1 chunk transposed: BT[kk][n] (lanes vary n -> conflict-free)
        for (int e = tid; e < 4096; e += 256) {
            int n = e & 255, kq = e >> 8;      // kq 0..15
            float4 v = *(const float4*)&W1[(size_t)n * H_ + kb + kq * 4];
            int k = kq * 4;
            BT[(k + 0) * 256 + n] = v.x;
            BT[(k + 1) * 256 + n] = v.y;
            BT[(k + 2) * 256 + n] = v.z;
            BT[(k + 3) * 256 + n] = v.w;
        }
        __syncthreads();

        for (int kk = 0; kk < 64; kk++) {
            int k = kb + kk;
            float a[8], bv[8];
            *(float4*)&a[0]  = *(const float4*)&AT[k * 64 + tm * 8];
            *(float4*)&a[4]  = *(const float4*)&AT[k * 64 + tm * 8 + 4];
            *(float4*)&bv[0] = *(const float4*)&BT[kk * 256 + tn * 8];
            *(float4*)&bv[4] = *(const float4*)&BT[kk * 256 + tn * 8 + 4];
#pragma unroll
            for (int i = 0; i < 8; i++)
#pragma unroll
                for (int j = 0; j < 8; j++)
                    acc[i][j] = fmaf(a[i], bv[j], acc[i][j]);
        }
    }
    __syncthreads();

    // ReLU + bias, write y1 transposed into AT (stride 65)
#pragma unroll
    for (int jj = 0; jj < 8; jj++) {
        float bb = b1[tn * 8 + jj];
#pragma unroll
        for (int i = 0; i < 8; i++) {
            float v = fmaxf(acc[i][jj] + bb, 0.0f);
            AT[(tn * 8 + jj) * 65 + tm * 8 + i] = v;
        }
    }
    __syncthreads();

    // ---- GEMM2: [64 x 64] = y1 @ W2^T, thread tile 8m x 2n ----
    float acc2[8][2];
#pragma unroll
    for (int i = 0; i < 8; i++) { acc2[i][0] = 0.0f; acc2[i][1] = 0.0f; }

    for (int kb = 0; kb < MLPH_; kb += 64) {
        // Stage W2 chunk transposed: BT[kk][d], d 0..63
        for (int e = tid; e < 1024; e += 256) {
            int d = e & 63, kq = e >> 6;       // kq 0..15
            float4 v = *(const float4*)&W2[(size_t)d * MLPH_ + kb + kq * 4];
            int k = kq * 4;
            BT[(k + 0) * 64 + d] = v.x;
            BT[(k + 1) * 64 + d] = v.y;
            BT[(k + 2) * 64 + d] = v.z;
            BT[(k + 3) * 64 + d] = v.w;
        }
        __syncthreads();

        for (int kk = 0; kk < 64; kk++) {
            int k = kb + kk;
            float b0v = BT[kk * 64 + tn * 2];
            float b1v = BT[kk * 64 + tn * 2 + 1];
#pragma unroll
            for (int i = 0; i < 8; i++) {
                float a = AT[k * 65 + tm * 8 + i];
                acc2[i][0] = fmaf(a, b0v, acc2[i][0]);
                acc2[i][1] = fmaf(a, b1v, acc2[i][1]);
            }
        }
        __syncthreads();
    }

    // Epilogue: +b2, *mask, store
    float bb0 = b2[tn * 2], bb1 = b2[tn * 2 + 1];
#pragma unroll
    for (int i = 0; i < 8; i++) {
        size_t row = row0 + tm * 8 + i;
        float mk = mask[row];
        float2 o;
        o.x = (acc2[i][0] + bb0) * mk;
        o.y = (acc2[i][1] + bb1) * mk;
        *(float2*)&out[row * DOUT_ + tn * 2] = o;
    }
}

// ---------------------------------------------------------------------------
extern "C" void kernel_launch(void* const* d_in, const int* in_sizes, int n_in,
                              void* d_out, int out_size) {
    const float* x    = (const float*)d_in[0];
    const float* mask = (const float*)d_in[1];
    const float* h0   = (const float*)d_in[2];
    const float* c0   = (const float*)d_in[3];
    const float* W_ih = (const float*)d_in[4];
    const float* W_hh = (const float*)d_in[5];
    const float* b_ih = (const float*)d_in[6];
    const float* b_hh = (const float*)d_in[7];
    const float* W1   = (const float*)d_in[8];
    const float* b1   = (const float*)d_in[9];
    const float* W2   = (const float*)d_in[10];
    const float* b2   = (const float*)d_in[11];
    float* out = (float*)d_out;

    cudaFuncSetAttribute(lstm_kernel, cudaFuncAttributeMaxDynamicSharedMemorySize,
                         LSTM_SMEM_BYTES);
    cudaFuncSetAttribute(mlp_kernel, cudaFuncAttributeMaxDynamicSharedMemorySize,
                         MLP_SMEM_BYTES);

    init_kernel<<<512, 256>>>(h0);
    lstm_kernel<<<128, 256, LSTM_SMEM_BYTES>>>(x, h0, c0, W_ih, W_hh, b_ih, b_hh);
    mlp_kernel<<<(B_ * T_) / 64, 256, MLP_SMEM_BYTES>>>(W1, b1, W2, b2, mask, out);
}

// round 11
// speedup vs baseline: 1.2211x; 1.2211x over previous
#include <cuda_runtime.h>
#include <cuda_bf16.h>

// Problem dims
#define B_    512
#define T_    1024
#define DIN_  64
#define H_    256
#define MLPH_ 256
#define DOUT_ 64

// ---------------- LSTM MMA config ----------------
// 16 groups x 8 CTAs; group = 32 batch rows; CTA = 32 units = 128 gate cols
// CTA: 128 threads = 4 warps, each warp m32 x n32, K = 320 (20 k-tiles of 16)
#define KT_  20
// smem (u32 offsets)
#define OFF_BHI 0            // B frags hi: 20kt x 4ng x 32lane x 8 = 20480 u32
#define OFF_BLO 20480        // B frags lo: 20480 u32
#define OFF_A   40960        // A frags hi+lo interleaved: 40blk x 32lane x 8 = 10240 u32
#define OFF_HT  51200        // h tile: 32 x 33 floats = 1056
#define LSTM_SMEM_BYTES ((51200 + 1056) * 4)   // 209024

// ---------------- MLP smem (unchanged from R9) ----------------
#define MLP_AT_FLOATS (256*65)
#define MLP_BT_FLOATS (64*256)
#define MLP_SMEM_BYTES ((MLP_AT_FLOATS + MLP_BT_FLOATS) * 4)  // 132096

// Device scratch (static; cudaMalloc forbidden)
__device__ float    g_hbuf[2][B_][H_];
__device__ float    g_hs[(size_t)B_ * T_ * H_];
__device__ unsigned g_bar[16];

__device__ __forceinline__ float sigf(float v) {
    return __fdividef(1.0f, 1.0f + __expf(-v));
}

__device__ __forceinline__ void mma16816(float* c, const unsigned* a, const unsigned* b) {
    asm volatile(
        "mma.sync.aligned.m16n8k16.row.col.f32.bf16.bf16.f32 "
        "{%0,%1,%2,%3},{%4,%5,%6,%7},{%8,%9},{%0,%1,%2,%3};\n"
        : "+f"(c[0]), "+f"(c[1]), "+f"(c[2]), "+f"(c[3])
        : "r"(a[0]), "r"(a[1]), "r"(a[2]), "r"(a[3]), "r"(b[0]), "r"(b[1]));
}

// split fp32 pair -> bf16x2 hi + bf16x2 lo (residual)
__device__ __forceinline__ void split_pack(float2 v, unsigned& uhi, unsigned& ulo) {
    __nv_bfloat16 hx = __float2bfloat16(v.x);
    __nv_bfloat16 hy = __float2bfloat16(v.y);
    __nv_bfloat16 lx = __float2bfloat16(v.x - __bfloat162float(hx));
    __nv_bfloat16 ly = __float2bfloat16(v.y - __bfloat162float(hy));
    uhi = (unsigned)__bfloat16_as_ushort(hx) | ((unsigned)__bfloat16_as_ushort(hy) << 16);
    ulo = (unsigned)__bfloat16_as_ushort(lx) | ((unsigned)__bfloat16_as_ushort(ly) << 16);
}

// ---------------------------------------------------------------------------
__global__ void init_kernel(const float* __restrict__ h0) {
    int i = blockIdx.x * 256 + threadIdx.x;
    if (i < B_ * H_) (&g_hbuf[0][0][0])[i] = h0[i];
    if (blockIdx.x == 0 && threadIdx.x < 16) g_bar[threadIdx.x] = 0u;
}

// ---------------------------------------------------------------------------
// Persistent LSTM with bf16x3 tensor-core GEMM. grid 128 (16 groups x 8), 128 thr
// ---------------------------------------------------------------------------
#define LOADFRAG(kt, bf) do {                                                  \
    const unsigned* _a = smU + OFF_A + lane * 8 + (kt) * 512;                  \
    *(uint4*)(ah[bf][0]) = *(const uint4*)(_a);                                \
    *(uint4*)(al[bf][0]) = *(const uint4*)(_a + 4);                            \
    *(uint4*)(ah[bf][1]) = *(const uint4*)(_a + 256);                          \
    *(uint4*)(al[bf][1]) = *(const uint4*)(_a + 260);                          \
    const unsigned* _b = smU + (kt) * 1024 + ng * 256 + lane * 8;              \
    *(uint4*)(bh[bf] + 0) = *(const uint4*)(_b);                               \
    *(uint4*)(bh[bf] + 4) = *(const uint4*)(_b + 4);                           \
    *(uint4*)(bl[bf] + 0) = *(const uint4*)(_b + OFF_BLO);                     \
    *(uint4*)(bl[bf] + 4) = *(const uint4*)(_b + OFF_BLO + 4);                 \
} while (0)

#define MMASTEP(bf) do {                                                       \
    _Pragma("unroll")                                                          \
    for (int mt = 0; mt < 2; mt++) {                                           \
        _Pragma("unroll")                                                      \
        for (int j = 0; j < 4; j++) {                                          \
            mma16816(acc[mt][j], ah[bf][mt], bh[bf] + j * 2);                  \
            mma16816(acc[mt][j], ah[bf][mt], bl[bf] + j * 2);                  \
            mma16816(acc[mt][j], al[bf][mt], bh[bf] + j * 2);                  \
        }                                                                      \
    }                                                                          \
} while (0)

__global__ void __launch_bounds__(128, 1) lstm_kernel(
    const float* __restrict__ x,    const float* __restrict__ c0,
    const float* __restrict__ W_ih, const float* __restrict__ W_hh,
    const float* __restrict__ b_ih, const float* __restrict__ b_hh)
{
    extern __shared__ unsigned smU[];
    float* htile = (float*)(smU + OFF_HT);   // [32 rows][33]

    const int tid  = threadIdx.x;
    const int p    = blockIdx.x >> 3;    // batch group 0..15
    const int q    = blockIdx.x & 7;     // unit CTA   0..7
    const int b0   = p * 32;
    const int u0   = q * 32;
    const int lane = tid & 31;
    const int ng   = tid >> 5;           // warp = n-group 0..3 (32 cols each)
    const int gid  = lane >> 2;          // 0..7
    const int tg   = lane & 3;           // 0..3

    // ---- one-time: fragment-pack weight slice (hi+lo) into SMEM ----
    // col mapping within warp's 32-block: c = gate*8 + usub
    // B frag: n(=usub) = ln>>2 ; k-pair = kt*16 + (ln&3)*2 + r*8
    for (int s = tid; s < 20480; s += 128) {
        int r   = s & 1;
        int j   = (s >> 1) & 3;      // gate tile
        int ln  = (s >> 3) & 31;
        int blk = s >> 8;            // kt*4 + ng
        int bng = blk & 3, kt = blk >> 2;
        int grow = j * H_ + u0 + bng * 8 + (ln >> 2);
        int k    = kt * 16 + (ln & 3) * 2 + r * 8;
        float2 wv = (k < H_) ? *(const float2*)&W_hh[(size_t)grow * H_ + k]
                             : *(const float2*)&W_ih[(size_t)grow * DIN_ + (k - H_)];
        unsigned uhi, ulo;
        split_pack(wv, uhi, ulo);
        smU[OFF_BHI + s] = uhi;
        smU[OFF_BLO + s] = ulo;
    }

    // Thread's output cells: rows = b0 + mt*16 + gid + s*8 ; units = u0 + ng*8 + tg*2 + e
    float bs[4][2];
#pragma unroll
    for (int j = 0; j < 4; j++)
#pragma unroll
        for (int e = 0; e < 2; e++) {
            int un = u0 + ng * 8 + tg * 2 + e;
            bs[j][e] = b_ih[j * H_ + un] + b_hh[j * H_ + un];
        }
    float cst[2][4];
#pragma unroll
    for (int mt = 0; mt < 2; mt++)
#pragma unroll
        for (int r = 0; r < 4; r++) {
            int row = b0 + mt * 16 + gid + (r >> 1) * 8;
            int un  = u0 + ng * 8 + tg * 2 + (r & 1);
            cst[mt][r] = c0[(size_t)row * H_ + un];
        }

    __syncthreads();

    unsigned cur = 0;
    for (int t = 0; t < T_; t++) {
        // ---- stage A = [h | x_t] as hi/lo fragments ----
        // ep -> (blk = kt*2+mt, ln, r): row = mt*16 + (ln>>2) + (r&1)*8
        //                               kpair = kt*16 + (ln&3)*2 + (r>>1)*8
        for (int ep = tid; ep < 5120; ep += 128) {
            int r   = ep & 3;
            int ln  = (ep >> 2) & 31;
            int blk = ep >> 7;           // 0..39
            int mt  = blk & 1, kt = blk >> 1;
            int row = b0 + mt * 16 + (ln >> 2) + (r & 1) * 8;
            int kb  = kt * 16 + (ln & 3) * 2 + (r >> 1) * 8;
            float2 v;
            if (kb < H_)
                v = __ldcg((const float2*)&g_hbuf[cur][row][kb]);
            else
                v = *(const float2*)&x[((size_t)row * T_ + t) * DIN_ + (kb - H_)];
            unsigned uhi, ulo;
            split_pack(v, uhi, ulo);
            int base = OFF_A + blk * 256 + ln * 8;
            smU[base + r]     = uhi;
            smU[base + 4 + r] = ulo;
        }
        __syncthreads();

        // ---- GEMM: 3-pass bf16 split, double-buffered fragments ----
        float acc[2][4][4];
#pragma unroll
        for (int mt = 0; mt < 2; mt++)
#pragma unroll
            for (int j = 0; j < 4; j++)
#pragma unroll
                for (int r = 0; r < 4; r++) acc[mt][j][r] = bs[j][r & 1];

        unsigned ah[2][2][4], al[2][2][4], bh[2][8], bl[2][8];
        LOADFRAG(0, 0);
#pragma unroll 2
        for (int kt = 0; kt < KT_; kt++) {
            int bf = kt & 1;
            if (kt + 1 < KT_) LOADFRAG(kt + 1, bf ^ 1);
            MMASTEP(bf);
        }

        // ---- pointwise LSTM cell -> h tile in smem ----
#pragma unroll
        for (int mt = 0; mt < 2; mt++)
#pragma unroll
            for (int r = 0; r < 4; r++) {
                float ig = sigf(acc[mt][0][r]);
                float fg = sigf(acc[mt][1][r]);
                float gg = tanhf(acc[mt][2][r]);
                float og = sigf(acc[mt][3][r]);
                float cn = fmaf(fg, cst[mt][r], ig * gg);
                cst[mt][r] = cn;
                float h = og * tanhf(cn);
                int rl = mt * 16 + gid + (r >> 1) * 8;
                int ul = ng * 8 + tg * 2 + (r & 1);
                htile[rl * 33 + ul] = h;
            }
        __syncthreads();

        // ---- coalesced writeout: h -> g_hbuf[nxt], g_hs ----
        unsigned nxt = cur ^ 1u;
        {
            int row = tid >> 2, seg = tid & 3;
            const float* hp = &htile[row * 33 + seg * 8];
            float4 v0, v1;
            v0.x = hp[0]; v0.y = hp[1]; v0.z = hp[2]; v0.w = hp[3];
            v1.x = hp[4]; v1.y = hp[5]; v1.z = hp[6]; v1.w = hp[7];
            int grow = b0 + row;
            *(float4*)&g_hbuf[nxt][grow][u0 + seg * 8]     = v0;
            *(float4*)&g_hbuf[nxt][grow][u0 + seg * 8 + 4] = v1;
            size_t o = ((size_t)grow * T_ + t) * H_ + u0 + seg * 8;
            *(float4*)&g_hs[o]     = v0;
            *(float4*)&g_hs[o + 4] = v1;
        }

        // ---- per-group barrier ----
        __threadfence();
        __syncthreads();
        if (tid == 0) {
            atomicAdd(&g_bar[p], 1u);
            unsigned target = 8u * (unsigned)(t + 1);
            unsigned v;
            do {
                asm volatile("ld.global.acquire.gpu.u32 %0, [%1];"
                             : "=r"(v) : "l"(g_bar + p));
            } while (v < target);
        }
        __syncthreads();
        cur = nxt;
    }
}

// ---------------------------------------------------------------------------
// Fused MLP (unchanged, proven): y = relu(hs@W1^T+b1)@W2^T+b2, *mask
// ---------------------------------------------------------------------------
__global__ void __launch_bounds__(256, 1) mlp_kernel(
    const float* __restrict__ W1, const float* __restrict__ b1,
    const float* __restrict__ W2, const float* __restrict__ b2,
    const float* __restrict__ mask, float* __restrict__ out)
{
    extern __shared__ float sm[];
    float* AT = sm;
    float* BT = sm + MLP_AT_FLOATS;

    const int tid = threadIdx.x;
    const size_t row0 = (size_t)blockIdx.x * 64;
    const int tm = tid >> 5;
    const int tn = tid & 31;

    for (int e = tid; e < 4096; e += 256) {
        int m = e & 63, kq = e >> 6;
        float4 v = *(const float4*)&g_hs[(row0 + m) * H_ + kq * 4];
        int k = kq * 4;
        AT[(k + 0) * 64 + m] = v.x;
        AT[(k + 1) * 64 + m] = v.y;
        AT[(k + 2) * 64 + m] = v.z;
        AT[(k + 3) * 64 + m] = v.w;
    }

    float acc[8][8];
#pragma unroll
    for (int i = 0; i < 8; i++)
#pragma unroll
        for (int j = 0; j < 8; j++) acc[i][j] = 0.0f;

    for (int kb = 0; kb < H_; kb += 64) {
        __syncthreads();
        for (int e = tid; e < 4096; e += 256) {
            int n = e & 255, kq = e >> 8;
            float4 v = *(const float4*)&W1[(size_t)n * H_ + kb + kq * 4];
            int k = kq * 4;
            BT[(k + 0) * 256 + n] = v.x;
            BT[(k + 1) * 256 + n] = v.y;
            BT[(k + 2) * 256 + n] = v.z;
            BT[(k + 3) * 256 + n] = v.w;
        }
        __syncthreads();

        for (int kk = 0; kk < 64; kk++) {
            int k = kb + kk;
            float a[8], bv[8];
            *(float4*)&a[0]  = *(const float4*)&AT[k * 64 + tm * 8];
            *(float4*)&a[4]  = *(const float4*)&AT[k * 64 + tm * 8 + 4];
            *(float4*)&bv[0] = *(const float4*)&BT[kk * 256 + tn * 8];
            *(float4*)&bv[4] = *(const float4*)&BT[kk * 256 + tn * 8 + 4];
#pragma unroll
            for (int i = 0; i < 8; i++)
#pragma unroll
                for (int j = 0; j < 8; j++)
                    acc[i][j] = fmaf(a[i], bv[j], acc[i][j]);
        }
    }
    __syncthreads();

#pragma unroll
    for (int jj = 0; jj < 8; jj++) {
        float bb = b1[tn * 8 + jj];
#pragma unroll
        for (int i = 0; i < 8; i++) {
            float v = fmaxf(acc[i][jj] + bb, 0.0f);
            AT[(tn * 8 + jj) * 65 + tm * 8 + i] = v;
        }
    }
    __syncthreads();

    float acc2[8][2];
#pragma unroll
    for (int i = 0; i < 8; i++) { acc2[i][0] = 0.0f; acc2[i][1] = 0.0f; }

    for (int kb = 0; kb < MLPH_; kb += 64) {
        for (int e = tid; e < 1024; e += 256) {
            int d = e & 63, kq = e >> 6;
            float4 v = *(const float4*)&W2[(size_t)d * MLPH_ + kb + kq * 4];
            int k = kq * 4;
            BT[(k + 0) * 64 + d] = v.x;
            BT[(k + 1) * 64 + d] = v.y;
            BT[(k + 2) * 64 + d] = v.z;
            BT[(k + 3) * 64 + d] = v.w;
        }
        __syncthreads();

        for (int kk = 0; kk < 64; kk++) {
            int k = kb + kk;
            float b0v = BT[kk * 64 + tn * 2];
            float b1v = BT[kk * 64 + tn * 2 + 1];
#pragma unroll
            for (int i = 0; i < 8; i++) {
                float a = AT[k * 65 + tm * 8 + i];
                acc2[i][0] = fmaf(a, b0v, acc2[i][0]);
                acc2[i][1] = fmaf(a, b1v, acc2[i][1]);
            }
        }
        __syncthreads();
    }

    float bb0 = b2[tn * 2], bb1 = b2[tn * 2 + 1];
#pragma unroll
    for (int i = 0; i < 8; i++) {
        size_t row = row0 + tm * 8 + i;
        float mk = mask[row];
        float2 o;
        o.x = (acc2[i][0] + bb0) * mk;
        o.y = (acc2[i][1] + bb1) * mk;
        *(float2*)&out[row * DOUT_ + tn * 2] = o;
    }
}

// ---------------------------------------------------------------------------
extern "C" void kernel_launch(void* const* d_in, const int* in_sizes, int n_in,
                              void* d_out, int out_size) {
    const float* x    = (const float*)d_in[0];
    const float* mask = (const float*)d_in[1];
    const float* h0   = (const float*)d_in[2];
    const float* c0   = (const float*)d_in[3];
    const float* W_ih = (const float*)d_in[4];
    const float* W_hh = (const float*)d_in[5];
    const float* b_ih = (const float*)d_in[6];
    const float* b_hh = (const float*)d_in[7];
    const float* W1   = (const float*)d_in[8];
    const float* b1   = (const float*)d_in[9];
    const float* W2   = (const float*)d_in[10];
    const float* b2   = (const float*)d_in[11];
    float* out = (float*)d_out;

    cudaFuncSetAttribute(lstm_kernel, cudaFuncAttributeMaxDynamicSharedMemorySize,
                         LSTM_SMEM_BYTES);
    cudaFuncSetAttribute(mlp_kernel, cudaFuncAttributeMaxDynamicSharedMemorySize,
                         MLP_SMEM_BYTES);

    init_kernel<<<512, 256>>>(h0);
    lstm_kernel<<<128, 128, LSTM_SMEM_BYTES>>>(x, c0, W_ih, W_hh, b_ih, b_hh);
    mlp_kernel<<<(B_ * T_) / 64, 256, MLP_SMEM_BYTES>>>(W1, b1, W2, b2, mask, out);
}

// round 13
// speedup vs baseline: 1.9399x; 1.5886x over previous
#include <cuda_runtime.h>
#include <cuda_bf16.h>

// Problem dims
#define B_    512
#define T_    1024
#define DIN_  64
#define H_    256
#define MLPH_ 256
#define DOUT_ 64

// LSTM: 16 groups x 8 CTAs; group = 32 batch rows; CTA = 32 units = 128 gate cols
// CTA: 256 threads = 8 warps (2 m-tiles x 4 n-groups), K = 320 (20 k-tiles)
#define KT_  20
// smem u32 offsets
#define OFF_BHI 0            // B frags hi: 20kt x 4ng x 32lane x 8 = 20480 u32
#define OFF_BLO 20480        // B frags lo
#define OFF_A   40960        // A frags: 40 blk x 256 u32 (hi 0..3, lo 4..7 per lane)
#define OFF_HT  51200        // h tile: 32 x 33 floats
#define LSTM_SMEM_BYTES ((51200 + 1056) * 4)   // 209024

// MLP smem (proven R9/R10 kernel)
#define MLP_AT_FLOATS (256*65)
#define MLP_BT_FLOATS (64*256)
#define MLP_SMEM_BYTES ((MLP_AT_FLOATS + MLP_BT_FLOATS) * 4)  // 132096

// Device scratch (static; cudaMalloc forbidden)
__device__ float    g_hs[(size_t)B_ * T_ * H_];        // 512 MB hidden states (for MLP)
__device__ unsigned g_hfrag[2][16][32][256];           // 1 MB  h fragments, double-buffered
__device__ unsigned g_xfrag[(size_t)T_ * 16 * 8 * 256];// 128 MB x fragments (all t)
__device__ unsigned g_bar[16];

__device__ __forceinline__ float sigf(float v) {
    return __fdividef(1.0f, 1.0f + __expf(-v));
}
__device__ __forceinline__ float tfast(float v) {
    float e = __expf(-2.0f * fabsf(v));
    return copysignf(__fdividef(1.0f - e, 1.0f + e), v);
}

__device__ __forceinline__ void mma16816(float* c, const unsigned* a, const unsigned* b) {
    asm volatile(
        "mma.sync.aligned.m16n8k16.row.col.f32.bf16.bf16.f32 "
        "{%0,%1,%2,%3},{%4,%5,%6,%7},{%8,%9},{%0,%1,%2,%3};\n"
        : "+f"(c[0]), "+f"(c[1]), "+f"(c[2]), "+f"(c[3])
        : "r"(a[0]), "r"(a[1]), "r"(a[2]), "r"(a[3]), "r"(b[0]), "r"(b[1]));
}

__device__ __forceinline__ void split_pack(float2 v, unsigned& uhi, unsigned& ulo) {
    __nv_bfloat16 hx = __float2bfloat16(v.x);
    __nv_bfloat16 hy = __float2bfloat16(v.y);
    __nv_bfloat16 lx = __float2bfloat16(v.x - __bfloat162float(hx));
    __nv_bfloat16 ly = __float2bfloat16(v.y - __bfloat162float(hy));
    uhi = (unsigned)__bfloat16_as_ushort(hx) | ((unsigned)__bfloat16_as_ushort(hy) << 16);
    ulo = (unsigned)__bfloat16_as_ushort(lx) | ((unsigned)__bfloat16_as_ushort(ly) << 16);
}

// ---------------------------------------------------------------------------
// init: pack h0 into fragment layout (phase 0), reset barriers.
// ---------------------------------------------------------------------------
__global__ void init_kernel(const float* __restrict__ h0) {
    unsigned s = blockIdx.x * 256 + threadIdx.x;   // 0..16383
    int ln = s & 31, blk = (s >> 5) & 31, p = (s >> 10) & 15;
    int kt = blk >> 1, mt = blk & 1, gid = ln >> 2, tg = ln & 3;
    unsigned hi[4], lo[4];
#pragma unroll
    for (int r = 0; r < 4; r++) {
        int row = p * 32 + mt * 16 + gid + (r & 1) * 8;
        int un  = kt * 16 + tg * 2 + (r >> 1) * 8;
        float2 v = *(const float2*)&h0[(size_t)row * H_ + un];
        split_pack(v, hi[r], lo[r]);
    }
    unsigned* dst = &g_hfrag[0][p][blk][ln * 8];
    *(uint4*)dst       = make_uint4(hi[0], hi[1], hi[2], hi[3]);
    *(uint4*)(dst + 4) = make_uint4(lo[0], lo[1], lo[2], lo[3]);
    if (s < 16) g_bar[s] = 0u;
}

// ---------------------------------------------------------------------------
// xfrag: pack x for ALL timesteps into fragment layout. grid 16384 x 256.
// ---------------------------------------------------------------------------
__global__ void xfrag_kernel(const float* __restrict__ x) {
    unsigned s = blockIdx.x * 256 + threadIdx.x;
    int ln = s & 31, blkx = (s >> 5) & 7, p = (s >> 8) & 15, t = s >> 12;
    int kt = blkx >> 1, mt = blkx & 1, gid = ln >> 2, tg = ln & 3;
    unsigned hi[4], lo[4];
#pragma unroll
    for (int r = 0; r < 4; r++) {
        int row = p * 32 + mt * 16 + gid + (r & 1) * 8;
        int kb  = kt * 16 + tg * 2 + (r >> 1) * 8;          // 0..63
        float2 v = *(const float2*)&x[((size_t)row * T_ + t) * DIN_ + kb];
        split_pack(v, hi[r], lo[r]);
    }
    unsigned* dst = g_xfrag + ((((size_t)t * 16 + p) * 8 + blkx) << 8) + ln * 8;
    *(uint4*)dst       = make_uint4(hi[0], hi[1], hi[2], hi[3]);
    *(uint4*)(dst + 4) = make_uint4(lo[0], lo[1], lo[2], lo[3]);
}

// ---------------------------------------------------------------------------
// Persistent LSTM. grid 128 (16 groups x 8), 256 threads (8 warps m16n32).
// ---------------------------------------------------------------------------
#define LOADFRAG(kt, bf) do {                                                  \
    const unsigned* _a = smU + OFF_A + (kt) * 512 + mtw * 256 + lane * 8;      \
    *(uint4*)(ah[bf]) = *(const uint4*)(_a);                                   \
    *(uint4*)(al[bf]) = *(const uint4*)(_a + 4);                               \
    const unsigned* _b = smU + (kt) * 1024 + ng * 256 + lane * 8;              \
    *(uint4*)(bh[bf])     = *(const uint4*)(_b);                               \
    *(uint4*)(bh[bf] + 4) = *(const uint4*)(_b + 4);                           \
    *(uint4*)(bl[bf])     = *(const uint4*)(_b + OFF_BLO);                     \
    *(uint4*)(bl[bf] + 4) = *(const uint4*)(_b + OFF_BLO + 4);                 \
} while (0)

#define MMASTEP(bf) do {                                                       \
    _Pragma("unroll")                                                          \
    for (int j = 0; j < 4; j++) {                                              \
        mma16816(acc[j], ah[bf], bh[bf] + j * 2);                              \
        mma16816(acc[j], ah[bf], bl[bf] + j * 2);                              \
        mma16816(acc[j], al[bf], bh[bf] + j * 2);                              \
    }                                                                          \
} while (0)

__global__ void __launch_bounds__(256, 1) lstm_kernel(
    const float* __restrict__ c0,   const float* __restrict__ W_ih,
    const float* __restrict__ W_hh, const float* __restrict__ b_ih,
    const float* __restrict__ b_hh)
{
    extern __shared__ unsigned smU[];
    float* htile = (float*)(smU + OFF_HT);   // [32][33]

    const int tid  = threadIdx.x;
    const int p    = blockIdx.x >> 3;
    const int q    = blockIdx.x & 7;
    const int b0   = p * 32;
    const int u0   = q * 32;
    const int lane = tid & 31;
    const int wid  = tid >> 5;
    const int mtw  = wid >> 2;        // m-tile 0..1
    const int ng   = wid & 3;         // n-group 0..3 (8 units each)
    const int gid  = lane >> 2;
    const int tg   = lane & 3;

    // ---- one-time: fragment-pack weight slice (hi+lo) into SMEM ----
    for (int s = tid; s < 20480; s += 256) {
        int r   = s & 1;
        int j   = (s >> 1) & 3;
        int ln  = (s >> 3) & 31;
        int blk = s >> 8;                // kt*4 + bng
        int bng = blk & 3, kt = blk >> 2;
        int grow = j * H_ + u0 + bng * 8 + (ln >> 2);
        int k    = kt * 16 + (ln & 3) * 2 + r * 8;
        float2 wv = (k < H_) ? *(const float2*)&W_hh[(size_t)grow * H_ + k]
                             : *(const float2*)&W_ih[(size_t)grow * DIN_ + (k - H_)];
        unsigned uhi, ulo;
        split_pack(wv, uhi, ulo);
        smU[OFF_BHI + s] = uhi;
        smU[OFF_BLO + s] = ulo;
    }

    // bias + cell state
    float bs[4][2];
#pragma unroll
    for (int j = 0; j < 4; j++)
#pragma unroll
        for (int e = 0; e < 2; e++) {
            int un = u0 + ng * 8 + tg * 2 + e;
            bs[j][e] = b_ih[j * H_ + un] + b_hh[j * H_ + un];
        }
    float cst[4];
#pragma unroll
    for (int rr = 0; rr < 4; rr++) {
        int row = b0 + mtw * 16 + gid + (rr >> 1) * 8;
        int un  = u0 + ng * 8 + tg * 2 + (rr & 1);
        cst[rr] = c0[(size_t)row * H_ + un];
    }
    __syncthreads();

    const int hblk = (q * 2 + (ng >> 1)) * 2 + mtw;   // this thread's h-frag block
    unsigned cur = 0;

    for (int t = 0; t < T_; t++) {
        // ---- A copy: h frags (blk 0..31) + x frags (blk 32..39) ----
        const unsigned* xsrc = g_xfrag + (((size_t)t * 16 + p) << 11);
        for (int i4 = tid; i4 < 2560; i4 += 256) {
            int blk = i4 >> 6, off = (i4 & 63) * 4;
            uint4 v;
            if (blk < 32)
                v = __ldcg((const uint4*)&g_hfrag[cur][p][blk][off]);
            else
                v = __ldcg((const uint4*)(xsrc + ((blk - 32) << 8) + off));
            *(uint4*)&smU[OFF_A + i4 * 4] = v;
        }
        __syncthreads();

        // ---- GEMM: 3-pass bf16 split, double-buffered fragments ----
        float acc[4][4];
#pragma unroll
        for (int j = 0; j < 4; j++)
#pragma unroll
            for (int rr = 0; rr < 4; rr++) acc[j][rr] = bs[j][rr & 1];

        unsigned ah[2][4], al[2][4], bh[2][8], bl[2][8];
        LOADFRAG(0, 0);
#pragma unroll 2
        for (int kt = 0; kt < KT_; kt++) {
            int bf = kt & 1;
            if (kt + 1 < KT_) LOADFRAG(kt + 1, bf ^ 1);
            MMASTEP(bf);
        }

        // ---- pointwise LSTM cell ----
        unsigned nxt = cur ^ 1u;
        float hv[4];
#pragma unroll
        for (int rr = 0; rr < 4; rr++) {
            float ig = sigf(acc[0][rr]);
            float fg = sigf(acc[1][rr]);
            float gg = tfast(acc[2][rr]);
            float og = sigf(acc[3][rr]);
            float cn = fmaf(fg, cst[rr], ig * gg);
            cst[rr] = cn;
            float h = og * tfast(cn);
            hv[rr] = h;
            htile[(mtw * 16 + gid + (rr >> 1) * 8) * 33 + ng * 8 + tg * 2 + (rr & 1)] = h;
        }
        // h -> fragment layout in global (direct, no re-split next step)
#pragma unroll
        for (int s = 0; s < 2; s++) {
            unsigned uhi, ulo;
            split_pack(make_float2(hv[s * 2], hv[s * 2 + 1]), uhi, ulo);
            int rA = s | ((ng & 1) << 1);
            unsigned* d = &g_hfrag[nxt][p][hblk][lane * 8 + rA];
            d[0] = uhi;
            d[4] = ulo;
        }
        __syncthreads();

        // ---- coalesced g_hs writeout (SCALAR htile reads: stride 33 is
        //      not 16B-aligned for odd rows — float4 here was the R11 bug) ----
        {
            int row = tid >> 3, seg = tid & 7;
            const float* hp = &htile[row * 33 + seg * 4];
            float4 v;
            v.x = hp[0]; v.y = hp[1]; v.z = hp[2]; v.w = hp[3];
            *(float4*)&g_hs[((size_t)(b0 + row) * T_ + t) * H_ + u0 + seg * 4] = v;
        }

        // ---- per-group barrier ----
        __threadfence();
        __syncthreads();
        if (tid == 0) {
            atomicAdd(&g_bar[p], 1u);
            unsigned target = 8u * (unsigned)(t + 1);
            unsigned v;
            do {
                asm volatile("ld.global.acquire.gpu.u32 %0, [%1];"
                             : "=r"(v) : "l"(g_bar + p));
            } while (v < target);
        }
        __syncthreads();
        cur = nxt;
    }
}

// ---------------------------------------------------------------------------
// Fused MLP (unchanged, proven): y = relu(hs@W1^T+b1)@W2^T+b2, *mask
// ---------------------------------------------------------------------------
__global__ void __launch_bounds__(256, 1) mlp_kernel(
    const float* __restrict__ W1, const float* __restrict__ b1,
    const float* __restrict__ W2, const float* __restrict__ b2,
    const float* __restrict__ mask, float* __restrict__ out)
{
    extern __shared__ float sm[];
    float* AT = sm;
    float* BT = sm + MLP_AT_FLOATS;

    const int tid = threadIdx.x;
    const size_t row0 = (size_t)blockIdx.x * 64;
    const int tm = tid >> 5;
    const int tn = tid & 31;

    for (int e = tid; e < 4096; e += 256) {
        int m = e & 63, kq = e >> 6;
        float4 v = *(const float4*)&g_hs[(row0 + m) * H_ + kq * 4];
        int k = kq * 4;
        AT[(k + 0) * 64 + m] = v.x;
        AT[(k + 1) * 64 + m] = v.y;
        AT[(k + 2) * 64 + m] = v.z;
        AT[(k + 3) * 64 + m] = v.w;
    }

    float acc[8][8];
#pragma unroll
    for (int i = 0; i < 8; i++)
#pragma unroll
        for (int j = 0; j < 8; j++) acc[i][j] = 0.0f;

    for (int kb = 0; kb < H_; kb += 64) {
        __syncthreads();
        for (int e = tid; e < 4096; e += 256) {
            int n = e & 255, kq = e >> 8;
            float4 v = *(const float4*)&W1[(size_t)n * H_ + kb + kq * 4];
            int k = kq * 4;
            BT[(k + 0) * 256 + n] = v.x;
            BT[(k + 1) * 256 + n] = v.y;
            BT[(k + 2) * 256 + n] = v.z;
            BT[(k + 3) * 256 + n] = v.w;
        }
        __syncthreads();

        for (int kk = 0; kk < 64; kk++) {
            int k = kb + kk;
            float a[8], bv[8];
            *(float4*)&a[0]  = *(const float4*)&AT[k * 64 + tm * 8];
            *(float4*)&a[4]  = *(const float4*)&AT[k * 64 + tm * 8 + 4];
            *(float4*)&bv[0] = *(const float4*)&BT[kk * 256 + tn * 8];
            *(float4*)&bv[4] = *(const float4*)&BT[kk * 256 + tn * 8 + 4];
#pragma unroll
            for (int i = 0; i < 8; i++)
#pragma unroll
                for (int j = 0; j < 8; j++)
                    acc[i][j] = fmaf(a[i], bv[j], acc[i][j]);
        }
    }
    __syncthreads();

#pragma unroll
    for (int jj = 0; jj < 8; jj++) {
        float bb = b1[tn * 8 + jj];
#pragma unroll
        for (int i = 0; i < 8; i++) {
            float v = fmaxf(acc[i][jj] + bb, 0.0f);
            AT[(tn * 8 + jj) * 65 + tm * 8 + i] = v;
        }
    }
    __syncthreads();

    float acc2[8][2];
#pragma unroll
    for (int i = 0; i < 8; i++) { acc2[i][0] = 0.0f; acc2[i][1] = 0.0f; }

    for (int kb = 0; kb < MLPH_; kb += 64) {
        for (int e = tid; e < 1024; e += 256) {
            int d = e & 63, kq = e >> 6;
            float4 v = *(const float4*)&W2[(size_t)d * MLPH_ + kb + kq * 4];
            int k = kq * 4;
            BT[(k + 0) * 64 + d] = v.x;
            BT[(k + 1) * 64 + d] = v.y;
            BT[(k + 2) * 64 + d] = v.z;
            BT[(k + 3) * 64 + d] = v.w;
        }
        __syncthreads();

        for (int kk = 0; kk < 64; kk++) {
            int k = kb + kk;
            float b0v = BT[kk * 64 + tn * 2];
            float b1v = BT[kk * 64 + tn * 2 + 1];
#pragma unroll
            for (int i = 0; i < 8; i++) {
                float a = AT[k * 65 + tm * 8 + i];
                acc2[i][0] = fmaf(a, b0v, acc2[i][0]);
                acc2[i][1] = fmaf(a, b1v, acc2[i][1]);
            }
        }
        __syncthreads();
    }

    float bb0 = b2[tn * 2], bb1 = b2[tn * 2 + 1];
#pragma unroll
    for (int i = 0; i < 8; i++) {
        size_t row = row0 + tm * 8 + i;
        float mk = mask[row];
        float2 o;
        o.x = (acc2[i][0] + bb0) * mk;
        o.y = (acc2[i][1] + bb1) * mk;
        *(float2*)&out[row * DOUT_ + tn * 2] = o;
    }
}

// ---------------------------------------------------------------------------
extern "C" void kernel_launch(void* const* d_in, const int* in_sizes, int n_in,
                              void* d_out, int out_size) {
    const float* x    = (const float*)d_in[0];
    const float* mask = (const float*)d_in[1];
    const float* h0   = (const float*)d_in[2];
    const float* c0   = (const float*)d_in[3];
    const float* W_ih = (const float*)d_in[4];
    const float* W_hh = (const float*)d_in[5];
    const float* b_ih = (const float*)d_in[6];
    const float* b_hh = (const float*)d_in[7];
    const float* W1   = (const float*)d_in[8];
    const float* b1   = (const float*)d_in[9];
    const float* W2   = (const float*)d_in[10];
    const float* b2   = (const float*)d_in[11];
    float* out = (float*)d_out;

    cudaFuncSetAttribute(lstm_kernel, cudaFuncAttributeMaxDynamicSharedMemorySize,
                         LSTM_SMEM_BYTES);
    cudaFuncSetAttribute(mlp_kernel, cudaFuncAttributeMaxDynamicSharedMemorySize,
                         MLP_SMEM_BYTES);

    init_kernel<<<64, 256>>>(h0);
    xfrag_kernel<<<16384, 256>>>(x);
    lstm_kernel<<<128, 256, LSTM_SMEM_BYTES>>>(c0, W_ih, W_hh, b_ih, b_hh);
    mlp_kernel<<<(B_ * T_) / 64, 256, MLP_SMEM_BYTES>>>(W1, b1, W2, b2, mask, out);
}

// round 14
// speedup vs baseline: 3.2720x; 1.6867x over previous
#include <cuda_runtime.h>
#include <cuda_bf16.h>

// Problem dims
#define B_    512
#define T_    1024
#define DIN_  64
#define H_    256
#define MLPH_ 256
#define DOUT_ 64

// ---------------- LSTM config ----------------
// 16 groups x 8 CTAs; group = 32 batch rows; CTA = 32 units = 128 gate cols
// 256 threads = 8 warps (mtw = wid>>2 m-tile, ng = wid&3 n-group of 32 cols)
// K = 320 = 20 k-tiles. Plane-major fragment layout (conflict-free LDS.128):
//  B block bb = kt*4 + ng (80 blocks x 512 u32): hi planes [(w>>2)*128 + ln*4 + (w&3)], lo +256
//  A block blk = kt*2 + mt (40 blocks x 256 u32): hi [ln*4 + r], lo +128
#define KT_   20
#define OFF_A 40960
#define LSTM_SMEM_BYTES (51200 * 4)   // 204800

// ---------------- MLP config ----------------
// 4096 CTAs x 512 thr; m=128 rows, GEMM1 k-chunked (2 x 128), fused GEMM2.
#define MW_OFF 16384
#define W2_OFF 32768
#define MLP_SMEM_BYTES (49152 * 4)    // 196608

// Device scratch (static; cudaMalloc forbidden)
__device__ float    g_hs[(size_t)B_ * T_ * H_];          // hidden states (MLP input)
__device__ unsigned g_hfrag[2][16][32][256];             // h frags, double-buffered
__device__ unsigned g_xfrag[(size_t)T_ * 16 * 8 * 256];  // x frags (all t)
__device__ unsigned g_bar[16];

__device__ __forceinline__ float sigf(float v) {
    return __fdividef(1.0f, 1.0f + __expf(-v));
}
__device__ __forceinline__ float tfast(float v) {
    float e = __expf(-2.0f * fabsf(v));
    return copysignf(__fdividef(1.0f - e, 1.0f + e), v);
}

__device__ __forceinline__ void mma16816(float* c, const unsigned* a, const unsigned* b) {
    asm volatile(
        "mma.sync.aligned.m16n8k16.row.col.f32.bf16.bf16.f32 "
        "{%0,%1,%2,%3},{%4,%5,%6,%7},{%8,%9},{%0,%1,%2,%3};\n"
        : "+f"(c[0]), "+f"(c[1]), "+f"(c[2]), "+f"(c[3])
        : "r"(a[0]), "r"(a[1]), "r"(a[2]), "r"(a[3]), "r"(b[0]), "r"(b[1]));
}

__device__ __forceinline__ void split_pack(float2 v, unsigned& uhi, unsigned& ulo) {
    __nv_bfloat16 hx = __float2bfloat16(v.x);
    __nv_bfloat16 hy = __float2bfloat16(v.y);
    __nv_bfloat16 lx = __float2bfloat16(v.x - __bfloat162float(hx));
    __nv_bfloat16 ly = __float2bfloat16(v.y - __bfloat162float(hy));
    uhi = (unsigned)__bfloat16_as_ushort(hx) | ((unsigned)__bfloat16_as_ushort(hy) << 16);
    ulo = (unsigned)__bfloat16_as_ushort(lx) | ((unsigned)__bfloat16_as_ushort(ly) << 16);
}

// ---------------------------------------------------------------------------
// init: pack h0 into fragment layout (phase 0), reset barriers.
// ---------------------------------------------------------------------------
__global__ void init_kernel(const float* __restrict__ h0) {
    unsigned s = blockIdx.x * 256 + threadIdx.x;   // 0..16383
    int ln = s & 31, blk = (s >> 5) & 31, p = (s >> 10) & 15;
    int kt = blk >> 1, mt = blk & 1, gid = ln >> 2, tg = ln & 3;
    unsigned hi[4], lo[4];
#pragma unroll
    for (int r = 0; r < 4; r++) {
        int row = p * 32 + mt * 16 + gid + (r & 1) * 8;
        int un  = kt * 16 + tg * 2 + (r >> 1) * 8;
        float2 v = *(const float2*)&h0[(size_t)row * H_ + un];
        split_pack(v, hi[r], lo[r]);
    }
    unsigned* dst = &g_hfrag[0][p][blk][ln * 4];
    *(uint4*)dst         = make_uint4(hi[0], hi[1], hi[2], hi[3]);
    *(uint4*)(dst + 128) = make_uint4(lo[0], lo[1], lo[2], lo[3]);
    if (s < 16) g_bar[s] = 0u;
}

// ---------------------------------------------------------------------------
// xfrag: pack x for ALL timesteps into fragment layout. grid 16384 x 256.
// ---------------------------------------------------------------------------
__global__ void xfrag_kernel(const float* __restrict__ x) {
    unsigned s = blockIdx.x * 256 + threadIdx.x;
    int ln = s & 31, blkx = (s >> 5) & 7, p = (s >> 8) & 15, t = s >> 12;
    int kt = blkx >> 1, mt = blkx & 1, gid = ln >> 2, tg = ln & 3;
    unsigned hi[4], lo[4];
#pragma unroll
    for (int r = 0; r < 4; r++) {
        int row = p * 32 + mt * 16 + gid + (r & 1) * 8;
        int kb  = kt * 16 + tg * 2 + (r >> 1) * 8;
        float2 v = *(const float2*)&x[((size_t)row * T_ + t) * DIN_ + kb];
        split_pack(v, hi[r], lo[r]);
    }
    unsigned* dst = g_xfrag + ((((size_t)t * 16 + p) * 8 + blkx) << 8) + ln * 4;
    *(uint4*)dst         = make_uint4(hi[0], hi[1], hi[2], hi[3]);
    *(uint4*)(dst + 128) = make_uint4(lo[0], lo[1], lo[2], lo[3]);
}

// ---------------------------------------------------------------------------
// Persistent LSTM. grid 128 (16 groups x 8), 256 threads (8 warps m16n32).
// ---------------------------------------------------------------------------
#define LOADFRAG(kt, bf) do {                                                  \
    const unsigned* _a = smU + OFF_A + ((kt) * 2 + mtw) * 256 + lane * 4;      \
    *(uint4*)(ah[bf]) = *(const uint4*)(_a);                                   \
    *(uint4*)(al[bf]) = *(const uint4*)(_a + 128);                             \
    const unsigned* _b = smU + ((kt) * 4 + ng) * 512 + lane * 4;               \
    *(uint4*)(bh[bf])     = *(const uint4*)(_b);                               \
    *(uint4*)(bh[bf] + 4) = *(const uint4*)(_b + 128);                         \
    *(uint4*)(bl[bf])     = *(const uint4*)(_b + 256);                         \
    *(uint4*)(bl[bf] + 4) = *(const uint4*)(_b + 384);                         \
} while (0)

#define MMASTEP(bf) do {                                                       \
    _Pragma("unroll")                                                          \
    for (int j = 0; j < 4; j++) {                                              \
        mma16816(acc[j], ah[bf], bh[bf] + j * 2);                              \
        mma16816(acc[j], ah[bf], bl[bf] + j * 2);                              \
        mma16816(acc[j], al[bf], bh[bf] + j * 2);                              \
    }                                                                          \
} while (0)

__global__ void __launch_bounds__(256, 1) lstm_kernel(
    const float* __restrict__ c0,   const float* __restrict__ W_ih,
    const float* __restrict__ W_hh, const float* __restrict__ b_ih,
    const float* __restrict__ b_hh)
{
    extern __shared__ unsigned smU[];

    const int tid  = threadIdx.x;
    const int p    = blockIdx.x >> 3;
    const int q    = blockIdx.x & 7;
    const int b0   = p * 32;
    const int u0   = q * 32;
    const int lane = tid & 31;
    const int wid  = tid >> 5;
    const int mtw  = wid >> 2;
    const int ng   = wid & 3;
    const int gid  = lane >> 2;
    const int tg   = lane & 3;

    // ---- one-time: fragment-pack weight slice (hi+lo, plane-major) ----
    for (int s = tid; s < 20480; s += 256) {
        int w  = s & 7;                  // j*2 + r
        int ln = (s >> 3) & 31;
        int bb = s >> 8;                 // kt*4 + bng
        int j = w >> 1, r = w & 1;
        int bng = bb & 3, kt = bb >> 2;
        int grow = j * H_ + u0 + bng * 8 + (ln >> 2);
        int k    = kt * 16 + (ln & 3) * 2 + r * 8;
        float2 wv = (k < H_) ? *(const float2*)&W_hh[(size_t)grow * H_ + k]
                             : *(const float2*)&W_ih[(size_t)grow * DIN_ + (k - H_)];
        unsigned uhi, ulo;
        split_pack(wv, uhi, ulo);
        int a = bb * 512 + (w >> 2) * 128 + ln * 4 + (w & 3);
        smU[a]       = uhi;
        smU[a + 256] = ulo;
    }

    // bias + cell state
    float bs[4][2];
#pragma unroll
    for (int j = 0; j < 4; j++)
#pragma unroll
        for (int e = 0; e < 2; e++) {
            int un = u0 + ng * 8 + tg * 2 + e;
            bs[j][e] = b_ih[j * H_ + un] + b_hh[j * H_ + un];
        }
    float cst[4];
#pragma unroll
    for (int rr = 0; rr < 4; rr++) {
        int row = b0 + mtw * 16 + gid + (rr >> 1) * 8;
        int un  = u0 + ng * 8 + tg * 2 + (rr & 1);
        cst[rr] = c0[(size_t)row * H_ + un];
    }
    __syncthreads();

    const int hblk = (q * 2 + (ng >> 1)) * 2 + mtw;
    const int urow0 = b0 + mtw * 16 + gid;
    const int ucol  = u0 + ng * 8 + tg * 2;

    for (int t = 0; t < T_; t++) {
        // ---- x-frag copy first (independent of barrier; overlaps spin) ----
        const unsigned* xsrc = g_xfrag + (((size_t)t * 16 + p) << 11);
        for (int i4 = tid; i4 < 512; i4 += 256)
            *(uint4*)&smU[OFF_A + 8192 + i4 * 4] = __ldcg((const uint4*)(xsrc + i4 * 4));

        // ---- wait for h_t from all 8 CTAs ----
        if (t > 0 && tid == 0) {
            unsigned target = 8u * (unsigned)t;
            unsigned v;
            do {
                asm volatile("ld.global.acquire.gpu.u32 %0, [%1];"
                             : "=r"(v) : "l"(g_bar + p));
            } while (v < target);
        }
        __syncthreads();

        // ---- h-frag copy ----
        const unsigned* hsrc = &g_hfrag[t & 1][p][0][0];
        for (int i4 = tid; i4 < 2048; i4 += 256)
            *(uint4*)&smU[OFF_A + i4 * 4] = __ldcg((const uint4*)(hsrc + i4 * 4));
        __syncthreads();

        // ---- GEMM: 3-pass bf16 split, double-buffered fragments ----
        float acc[4][4];
#pragma unroll
        for (int j = 0; j < 4; j++)
#pragma unroll
            for (int rr = 0; rr < 4; rr++) acc[j][rr] = bs[j][rr & 1];

        unsigned ah[2][4], al[2][4], bh[2][8], bl[2][8];
        LOADFRAG(0, 0);
#pragma unroll 2
        for (int kt = 0; kt < KT_; kt++) {
            int bf = kt & 1;
            if (kt + 1 < KT_) LOADFRAG(kt + 1, bf ^ 1);
            MMASTEP(bf);
        }

        // ---- pointwise LSTM cell ----
        int nb = (t + 1) & 1;
        float hv[4];
#pragma unroll
        for (int rr = 0; rr < 4; rr++) {
            float ig = sigf(acc[0][rr]);
            float fg = sigf(acc[1][rr]);
            float gg = tfast(acc[2][rr]);
            float og = sigf(acc[3][rr]);
            float cn = fmaf(fg, cst[rr], ig * gg);
            cst[rr] = cn;
            hv[rr] = og * tfast(cn);
        }
        // h -> fragment layout in global (plane-major)
#pragma unroll
        for (int s = 0; s < 2; s++) {
            unsigned uhi, ulo;
            split_pack(make_float2(hv[s * 2], hv[s * 2 + 1]), uhi, ulo);
            int rA = s | ((ng & 1) << 1);
            unsigned* d = &g_hfrag[nb][p][hblk][lane * 4 + rA];
            d[0]   = uhi;
            d[128] = ulo;
        }
        // h -> g_hs (direct; 32B contiguous per row-warp segment)
        *(float2*)&g_hs[((size_t)urow0 * T_ + t) * H_ + ucol]       = make_float2(hv[0], hv[1]);
        *(float2*)&g_hs[((size_t)(urow0 + 8) * T_ + t) * H_ + ucol] = make_float2(hv[2], hv[3]);

        // ---- release (bar.sync orders all threads' stores before it) ----
        __syncthreads();
        if (tid == 0)
            asm volatile("red.release.gpu.global.add.u32 [%0], %1;"
                         :: "l"(g_bar + p), "r"(1u) : "memory");
    }
}

// ---------------------------------------------------------------------------
// MLP with bf16x3 tensor cores: y = relu(hs@W1^T+b1)@W2^T+b2, *mask
// grid 4096 (128-row tiles), 512 threads = 16 warps (mw = wid&7, nh = wid>>3)
// ---------------------------------------------------------------------------
__global__ void __launch_bounds__(512, 1) mlp_kernel(
    const float* __restrict__ W1, const float* __restrict__ b1,
    const float* __restrict__ W2, const float* __restrict__ b2,
    const float* __restrict__ mask, float* __restrict__ out)
{
    extern __shared__ unsigned smU[];

    const int tid  = threadIdx.x;
    const int lane = tid & 31;
    const int wid  = tid >> 5;
    const int gid  = lane >> 2;
    const int tg   = lane & 3;
    const int mw   = wid & 7;
    const int nh   = wid >> 3;
    const size_t row0 = (size_t)blockIdx.x * 128;

    float acc[4][4][4];
#pragma unroll
    for (int bg = 0; bg < 4; bg++)
#pragma unroll
        for (int j = 0; j < 4; j++)
#pragma unroll
            for (int rr = 0; rr < 4; rr++) acc[bg][j][rr] = 0.0f;

    // ---- GEMM1: 2 k-chunks of 128 ----
    for (int c = 0; c < 2; c++) {
        // stage A chunk (64 blocks x 256 u32)
        for (int s = tid; s < 8192; s += 512) {
            int r = s & 3, ln = (s >> 2) & 31, ab = s >> 7;
            int mt = ab & 7, kt = ab >> 3;
            size_t row = row0 + mt * 16 + (ln >> 2) + (r & 1) * 8;
            int k = c * 128 + kt * 16 + (ln & 3) * 2 + (r >> 1) * 8;
            float2 v = *(const float2*)&g_hs[row * H_ + k];
            unsigned uhi, ulo;
            split_pack(v, uhi, ulo);
            smU[ab * 256 + ln * 4 + r]       = uhi;
            smU[ab * 256 + 128 + ln * 4 + r] = ulo;
        }
        // stage W1 chunk (64 blocks x 512 u32)
        for (int s = tid; s < 16384; s += 512) {
            int w = s & 7, ln = (s >> 3) & 31, wb = s >> 8;
            int bg = wb & 7, kt = wb >> 3;
            int n = bg * 32 + (w >> 1) * 8 + (ln >> 2);
            int k = c * 128 + kt * 16 + (ln & 3) * 2 + (w & 1) * 8;
            float2 v = *(const float2*)&W1[(size_t)n * H_ + k];
            unsigned uhi, ulo;
            split_pack(v, uhi, ulo);
            int a = MW_OFF + wb * 512 + (w >> 2) * 128 + ln * 4 + (w & 3);
            smU[a]       = uhi;
            smU[a + 256] = ulo;
        }
        __syncthreads();

        for (int kt = 0; kt < 8; kt++) {
            const unsigned* _a = smU + (kt * 8 + mw) * 256 + lane * 4;
            unsigned ah[4], al[4];
            *(uint4*)ah = *(const uint4*)_a;
            *(uint4*)al = *(const uint4*)(_a + 128);
#pragma unroll
            for (int bg = 0; bg < 4; bg++) {
                const unsigned* _b = smU + MW_OFF + (kt * 8 + nh * 4 + bg) * 512 + lane * 4;
                unsigned bh[8], bl[8];
                *(uint4*)(bh)     = *(const uint4*)(_b);
                *(uint4*)(bh + 4) = *(const uint4*)(_b + 128);
                *(uint4*)(bl)     = *(const uint4*)(_b + 256);
                *(uint4*)(bl + 4) = *(const uint4*)(_b + 384);
#pragma unroll
                for (int j = 0; j < 4; j++) {
                    mma16816(acc[bg][j], ah, bh + j * 2);
                    mma16816(acc[bg][j], ah, bl + j * 2);
                    mma16816(acc[bg][j], al, bh + j * 2);
                }
            }
        }
        __syncthreads();
    }

    // ---- stage W2 (32 blocks x 512 u32) ----
    for (int s = tid; s < 8192; s += 512) {
        int w = s & 7, ln = (s >> 3) & 31, wb = s >> 8;
        int bg2 = wb & 1, kt2 = wb >> 1;
        int n = bg2 * 32 + (w >> 1) * 8 + (ln >> 2);
        int k = kt2 * 16 + (ln & 3) * 2 + (w & 1) * 8;
        float2 v = *(const float2*)&W2[(size_t)n * MLPH_ + k];
        unsigned uhi, ulo;
        split_pack(v, uhi, ulo);
        int a = W2_OFF + wb * 512 + (w >> 2) * 128 + ln * 4 + (w & 3);
        smU[a]       = uhi;
        smU[a + 256] = ulo;
    }

    // ---- epilogue1: bias + relu -> y1 fragments (128 blocks x 256 u32 at 0) ----
#pragma unroll
    for (int bg = 0; bg < 4; bg++)
#pragma unroll
        for (int j = 0; j < 4; j++) {
            int bgp = nh * 4 + bg;
            int colb = bgp * 32 + j * 8 + tg * 2;
            float ba = b1[colb], bbv = b1[colb + 1];
            float v00 = fmaxf(acc[bg][j][0] + ba, 0.0f);
            float v01 = fmaxf(acc[bg][j][1] + bbv, 0.0f);
            float v10 = fmaxf(acc[bg][j][2] + ba, 0.0f);
            float v11 = fmaxf(acc[bg][j][3] + bbv, 0.0f);
            int yb = (bgp * 2 + (j >> 1)) * 8 + mw;
            int rb = (j & 1) * 2;
            unsigned uhi, ulo;
            split_pack(make_float2(v00, v01), uhi, ulo);
            smU[yb * 256 + lane * 4 + rb]       = uhi;
            smU[yb * 256 + 128 + lane * 4 + rb] = ulo;
            split_pack(make_float2(v10, v11), uhi, ulo);
            smU[yb * 256 + lane * 4 + rb + 1]       = uhi;
            smU[yb * 256 + 128 + lane * 4 + rb + 1] = ulo;
        }
    __syncthreads();

    // ---- GEMM2: m128 n64 k256 ----
    float acc2[4][4];
#pragma unroll
    for (int j = 0; j < 4; j++)
#pragma unroll
        for (int rr = 0; rr < 4; rr++) acc2[j][rr] = 0.0f;

    for (int kt2 = 0; kt2 < 16; kt2++) {
        const unsigned* _a = smU + (kt2 * 8 + mw) * 256 + lane * 4;
        unsigned ah[4], al[4];
        *(uint4*)ah = *(const uint4*)_a;
        *(uint4*)al = *(const uint4*)(_a + 128);
        const unsigned* _b = smU + W2_OFF + (kt2 * 2 + nh) * 512 + lane * 4;
        unsigned bh[8], bl[8];
        *(uint4*)(bh)     = *(const uint4*)(_b);
        *(uint4*)(bh + 4) = *(const uint4*)(_b + 128);
        *(uint4*)(bl)     = *(const uint4*)(_b + 256);
        *(uint4*)(bl + 4) = *(const uint4*)(_b + 384);
#pragma unroll
        for (int j = 0; j < 4; j++) {
            mma16816(acc2[j], ah, bh + j * 2);
            mma16816(acc2[j], ah, bl + j * 2);
            mma16816(acc2[j], al, bh + j * 2);
        }
    }

    // ---- epilogue2: + b2, * mask, store ----
    size_t r0 = row0 + mw * 16 + gid;
    size_t r1 = r0 + 8;
    float m0 = mask[r0], m1 = mask[r1];
#pragma unroll
    for (int j = 0; j < 4; j++) {
        int col = nh * 32 + j * 8 + tg * 2;
        float bb0 = b2[col], bb1 = b2[col + 1];
        *(float2*)&out[r0 * DOUT_ + col] =
            make_float2((acc2[j][0] + bb0) * m0, (acc2[j][1] + bb1) * m0);
        *(float2*)&out[r1 * DOUT_ + col] =
            make_float2((acc2[j][2] + bb0) * m1, (acc2[j][3] + bb1) * m1);
    }
}

// ---------------------------------------------------------------------------
extern "C" void kernel_launch(void* const* d_in, const int* in_sizes, int n_in,
                              void* d_out, int out_size) {
    const float* x    = (const float*)d_in[0];
    const float* mask = (const float*)d_in[1];
    const float* h0   = (const float*)d_in[2];
    const float* c0   = (const float*)d_in[3];
    const float* W_ih = (const float*)d_in[4];
    const float* W_hh = (const float*)d_in[5];
    const float* b_ih = (const float*)d_in[6];
    const float* b_hh = (const float*)d_in[7];
    const float* W1   = (const float*)d_in[8];
    const float* b1   = (const float*)d_in[9];
    const float* W2   = (const float*)d_in[10];
    const float* b2   = (const float*)d_in[11];
    float* out = (float*)d_out;

    cudaFuncSetAttribute(lstm_kernel, cudaFuncAttributeMaxDynamicSharedMemorySize,
                         LSTM_SMEM_BYTES);
    cudaFuncSetAttribute(mlp_kernel, cudaFuncAttributeMaxDynamicSharedMemorySize,
                         MLP_SMEM_BYTES);

    init_kernel<<<64, 256>>>(h0);
    xfrag_kernel<<<16384, 256>>>(x);
    lstm_kernel<<<128, 256, LSTM_SMEM_BYTES>>>(c0, W_ih, W_hh, b_ih, b_hh);
    mlp_kernel<<<(B_ * T_) / 128, 512, MLP_SMEM_BYTES>>>(W1, b1, W2, b2, mask, out);
}